// round 1
// baseline (speedup 1.0000x reference)
#include <cuda_runtime.h>
#include <cstdint>

#define NTHREADS 512

static constexpr int L  = 64;
static constexpr int D  = 128;
static constexpr int H  = 8;
static constexpr int DK = 16;

// Shared memory layout (floats):
//   xq   [64][128]  @ 0        (kept for residual)
//   xk   [64][128]  @ 8192     (reused as obuf in epilogue)
//   tvb  [64][128]  @ 16384
//   ctb  [64][128]  @ 24576
//   scratch         @ 32768  (14592 floats):
//     sh  [64][68], wqh/wkh/wvh [128][16], qh/kh/vh [64][16], xth [64][16]
static constexpr int SMEM_FLOATS = 32768 + 64*68 + 3*2048 + 4*1024;  // 47360
static constexpr int SMEM_BYTES  = SMEM_FLOATS * 4;                  // 189440

__global__ void __launch_bounds__(NTHREADS, 1)
fused_attn_kernel(const float* __restrict__ xq_g,
                  const float* __restrict__ xk_g,
                  const float* __restrict__ xt_g,
                  const float* __restrict__ Wq,  const float* __restrict__ bq,
                  const float* __restrict__ Wk,  const float* __restrict__ bk,
                  const float* __restrict__ Wv,  const float* __restrict__ bv,
                  const float* __restrict__ Wot, const float* __restrict__ bot,
                  const float* __restrict__ Wtg, const float* __restrict__ btg,
                  const float* __restrict__ g_time, const float* __restrict__ b_time,
                  const float* __restrict__ g_tgt,  const float* __restrict__ b_tgt,
                  float* __restrict__ out, int BN)
{
    extern __shared__ float sm[];
    float* xq  = sm;            // [64][128]
    float* xk  = sm + 8192;     // [64][128] -> obuf in epilogue
    float* tvb = sm + 16384;    // [64][128]
    float* ctb = sm + 24576;    // [64][128]
    float* scratch = sm + 32768;
    float* sh  = scratch;          // [64][68]
    float* wqh = scratch + 4352;   // [128][16]
    float* wkh = wqh + 2048;
    float* wvh = wkh + 2048;
    float* qh  = wvh + 2048;       // [64][16]
    float* kh  = qh + 1024;
    float* vh  = kh + 1024;
    float* xth = vh + 1024;        // [64][16]

    const int bn  = blockIdx.x;
    const int tid = threadIdx.x;

    const float* xq_src = xq_g + (size_t)bn * (L*D);
    const float* xk_src = xk_g + (size_t)bn * (L*D);
    const float* xt_src = xt_g + (size_t)bn * (L*D);

    const size_t attnElems = (size_t)BN * H * (L*L);
    float* tv_base = out + attnElems + (size_t)bn * (L*D);
    float* ct_base = out + attnElems + (size_t)BN * (L*D) + (size_t)bn * (L*D);

    // Load x_q, x_k tiles
    for (int i = tid; i < (L*D)/4; i += NTHREADS) {
        reinterpret_cast<float4*>(xq)[i] = reinterpret_cast<const float4*>(xq_src)[i];
        reinterpret_cast<float4*>(xk)[i] = reinterpret_cast<const float4*>(xk_src)[i];
    }
    __syncthreads();

    // ---------------- per-head stage ----------------
    for (int h = 0; h < H; ++h) {
        // stage W slices [128][16] for q,k,v and target slice [64][16]
        for (int i = tid; i < 512; i += NTHREADS) {   // 2048 floats -> 512 float4
            int d = i >> 2, c4 = i & 3;
            reinterpret_cast<float4*>(wqh)[i] =
                *(reinterpret_cast<const float4*>(Wq + d*D + h*DK) + c4);
            reinterpret_cast<float4*>(wkh)[i] =
                *(reinterpret_cast<const float4*>(Wk + d*D + h*DK) + c4);
            reinterpret_cast<float4*>(wvh)[i] =
                *(reinterpret_cast<const float4*>(Wv + d*D + h*DK) + c4);
        }
        for (int i = tid; i < 256; i += NTHREADS) {   // 1024 floats -> 256 float4
            int r = i >> 2, c4 = i & 3;
            reinterpret_cast<float4*>(xth)[i] =
                *(reinterpret_cast<const float4*>(xt_src + r*D + h*DK) + c4);
        }
        __syncthreads();

        // q_h, k_h, v_h : [64][16] = x @ Wslice + bias
        {
            const int c  = tid & 15;
            const int rb = tid >> 4;      // 0..31
            const int r0 = rb*2, r1 = r0 + 1;
            float aq0=0.f, aq1=0.f, ak0=0.f, ak1=0.f, av0=0.f, av1=0.f;
            for (int d0 = 0; d0 < D; d0 += 4) {
                float4 xa0 = *reinterpret_cast<const float4*>(xq + r0*D + d0);
                float4 xa1 = *reinterpret_cast<const float4*>(xq + r1*D + d0);
                float4 xb0 = *reinterpret_cast<const float4*>(xk + r0*D + d0);
                float4 xb1 = *reinterpret_cast<const float4*>(xk + r1*D + d0);
                float a0v[4], a1v[4], b0v[4], b1v[4];
                a0v[0]=xa0.x; a0v[1]=xa0.y; a0v[2]=xa0.z; a0v[3]=xa0.w;
                a1v[0]=xa1.x; a1v[1]=xa1.y; a1v[2]=xa1.z; a1v[3]=xa1.w;
                b0v[0]=xb0.x; b0v[1]=xb0.y; b0v[2]=xb0.z; b0v[3]=xb0.w;
                b1v[0]=xb1.x; b1v[1]=xb1.y; b1v[2]=xb1.z; b1v[3]=xb1.w;
                #pragma unroll
                for (int dd = 0; dd < 4; ++dd) {
                    float wq_ = wqh[(d0+dd)*DK + c];
                    float wk_ = wkh[(d0+dd)*DK + c];
                    float wv_ = wvh[(d0+dd)*DK + c];
                    aq0 += a0v[dd]*wq_;  aq1 += a1v[dd]*wq_;
                    ak0 += b0v[dd]*wk_;  ak1 += b1v[dd]*wk_;
                    av0 += b0v[dd]*wv_;  av1 += b1v[dd]*wv_;
                }
            }
            float bq_ = bq[h*DK + c], bk_ = bk[h*DK + c], bv_ = bv[h*DK + c];
            qh[r0*DK + c] = aq0 + bq_;  qh[r1*DK + c] = aq1 + bq_;
            kh[r0*DK + c] = ak0 + bk_;  kh[r1*DK + c] = ak1 + bk_;
            vh[r0*DK + c] = av0 + bv_;  vh[r1*DK + c] = av1 + bv_;
        }
        __syncthreads();

        // S_h [64][64] = q_h @ k_h^T * 0.25 ; write to smem + global attn output
        {
            const int kc = tid & 63;
            const int rg = tid >> 6;     // 0..7
            float kk[16];
            #pragma unroll
            for (int j = 0; j < 4; ++j) {
                float4 kv = *reinterpret_cast<const float4*>(kh + kc*DK + j*4);
                kk[4*j+0]=kv.x; kk[4*j+1]=kv.y; kk[4*j+2]=kv.z; kk[4*j+3]=kv.w;
            }
            float* attn_base = out + ((size_t)bn*H + h) * (L*L);
            #pragma unroll
            for (int i = 0; i < 8; ++i) {
                int r = rg*8 + i;
                float acc = 0.f;
                #pragma unroll
                for (int j = 0; j < 4; ++j) {
                    float4 qv = *reinterpret_cast<const float4*>(qh + r*DK + j*4);
                    acc += qv.x*kk[4*j] + qv.y*kk[4*j+1] + qv.z*kk[4*j+2] + qv.w*kk[4*j+3];
                }
                acc *= 0.25f;
                sh[r*68 + kc] = acc;
                attn_base[r*L + kc] = acc;
            }
        }
        __syncthreads();

        // tv_h = S_h @ v_h ; ct_h = S_h @ xt_h  -> accumulate head columns
        {
            const int c  = tid & 15;
            const int rb = tid >> 4;
            const int r0 = rb*2, r1 = r0 + 1;
            float atv0=0.f, atv1=0.f, act0=0.f, act1=0.f;
            for (int k0 = 0; k0 < L; k0 += 4) {
                float4 s0 = *reinterpret_cast<const float4*>(sh + r0*68 + k0);
                float4 s1 = *reinterpret_cast<const float4*>(sh + r1*68 + k0);
                float s0v[4], s1v[4];
                s0v[0]=s0.x; s0v[1]=s0.y; s0v[2]=s0.z; s0v[3]=s0.w;
                s1v[0]=s1.x; s1v[1]=s1.y; s1v[2]=s1.z; s1v[3]=s1.w;
                #pragma unroll
                for (int q = 0; q < 4; ++q) {
                    float vv = vh[(k0+q)*DK + c];
                    float tt = xth[(k0+q)*DK + c];
                    atv0 += s0v[q]*vv;  atv1 += s1v[q]*vv;
                    act0 += s0v[q]*tt;  act1 += s1v[q]*tt;
                }
            }
            tvb[r0*D + h*DK + c] = atv0;  tvb[r1*D + h*DK + c] = atv1;
            ctb[r0*D + h*DK + c] = act0;  ctb[r1*D + h*DK + c] = act1;
        }
        __syncthreads();
    }

    // ---------------- epilogue: output projections + LayerNorm ----------------
    float* obuf = xk;   // xk no longer needed
    for (int br = 0; br < 2; ++br) {
        const float* src  = br ? ctb : tvb;
        const float* W    = br ? Wtg : Wot;
        const float* bias = br ? btg : bot;

        for (int half = 0; half < 2; ++half) {
            __syncthreads();   // prior scratch/obuf consumers done
            // stage W[:, half*64 : half*64+64] -> ws [128][64]
            float* ws = scratch;
            for (int i = tid; i < (128*64)/4; i += NTHREADS) {  // 2048 float4
                int d = i >> 4, c4 = i & 15;
                reinterpret_cast<float4*>(ws)[i] =
                    *(reinterpret_cast<const float4*>(W + d*D + half*64) + c4);
            }
            __syncthreads();

            const int c0 = (tid & 15) * 4;
            const int rb = tid >> 4;
            const int r0 = rb*2, r1 = r0 + 1;
            float acc0[4], acc1[4];
            #pragma unroll
            for (int j = 0; j < 4; ++j) {
                acc0[j] = bias[half*64 + c0 + j];
                acc1[j] = acc0[j];
            }
            for (int d0 = 0; d0 < D; d0 += 4) {
                float4 a0 = *reinterpret_cast<const float4*>(src + r0*D + d0);
                float4 a1 = *reinterpret_cast<const float4*>(src + r1*D + d0);
                float a0v[4], a1v[4];
                a0v[0]=a0.x; a0v[1]=a0.y; a0v[2]=a0.z; a0v[3]=a0.w;
                a1v[0]=a1.x; a1v[1]=a1.y; a1v[2]=a1.z; a1v[3]=a1.w;
                #pragma unroll
                for (int dd = 0; dd < 4; ++dd) {
                    float4 w4 = *reinterpret_cast<const float4*>(ws + (d0+dd)*64 + c0);
                    acc0[0] += a0v[dd]*w4.x;  acc0[1] += a0v[dd]*w4.y;
                    acc0[2] += a0v[dd]*w4.z;  acc0[3] += a0v[dd]*w4.w;
                    acc1[0] += a1v[dd]*w4.x;  acc1[1] += a1v[dd]*w4.y;
                    acc1[2] += a1v[dd]*w4.z;  acc1[3] += a1v[dd]*w4.w;
                }
            }
            if (br == 0) {  // residual (time branch only)
                #pragma unroll
                for (int j = 0; j < 4; ++j) {
                    acc0[j] += xq[r0*D + half*64 + c0 + j];
                    acc1[j] += xq[r1*D + half*64 + c0 + j];
                }
            }
            *reinterpret_cast<float4*>(obuf + r0*D + half*64 + c0) =
                make_float4(acc0[0], acc0[1], acc0[2], acc0[3]);
            *reinterpret_cast<float4*>(obuf + r1*D + half*64 + c0) =
                make_float4(acc1[0], acc1[1], acc1[2], acc1[3]);
        }
        __syncthreads();

        // LayerNorm per row (population variance, eps 1e-5)
        {
            const float* g = br ? g_tgt : g_time;
            const float* b = br ? b_tgt : b_time;
            float* dst = br ? ct_base : tv_base;
            const int warp = tid >> 5, lane = tid & 31;
            #pragma unroll
            for (int i = 0; i < 4; ++i) {
                int r = warp*4 + i;
                float4 x = *reinterpret_cast<const float4*>(obuf + r*D + lane*4);
                float s1 = x.x + x.y + x.z + x.w;
                float s2 = x.x*x.x + x.y*x.y + x.z*x.z + x.w*x.w;
                #pragma unroll
                for (int o = 16; o; o >>= 1) {
                    s1 += __shfl_xor_sync(0xffffffffu, s1, o);
                    s2 += __shfl_xor_sync(0xffffffffu, s2, o);
                }
                float mean = s1 * (1.0f/128.0f);
                float var  = s2 * (1.0f/128.0f) - mean*mean;
                float rstd = rsqrtf(var + 1e-5f);
                float4 gv = *reinterpret_cast<const float4*>(g + lane*4);
                float4 bv2 = *reinterpret_cast<const float4*>(b + lane*4);
                float4 y;
                y.x = (x.x - mean)*rstd*gv.x + bv2.x;
                y.y = (x.y - mean)*rstd*gv.y + bv2.y;
                y.z = (x.z - mean)*rstd*gv.z + bv2.z;
                y.w = (x.w - mean)*rstd*gv.w + bv2.w;
                *reinterpret_cast<float4*>(dst + r*D + lane*4) = y;
            }
        }
        __syncthreads();  // obuf reused by next branch
    }
}

extern "C" void kernel_launch(void* const* d_in, const int* in_sizes, int n_in,
                              void* d_out, int out_size) {
    const float* xq   = (const float*)d_in[0];
    const float* xk   = (const float*)d_in[1];
    const float* xt   = (const float*)d_in[2];
    const float* Wq   = (const float*)d_in[3];
    const float* bq   = (const float*)d_in[4];
    const float* Wk   = (const float*)d_in[5];
    const float* bk   = (const float*)d_in[6];
    const float* Wv   = (const float*)d_in[7];
    const float* bv   = (const float*)d_in[8];
    const float* Wot  = (const float*)d_in[9];
    const float* bot  = (const float*)d_in[10];
    const float* Wtg  = (const float*)d_in[11];
    const float* btg  = (const float*)d_in[12];
    const float* g_time = (const float*)d_in[13];
    const float* b_time = (const float*)d_in[14];
    const float* g_tgt  = (const float*)d_in[15];
    const float* b_tgt  = (const float*)d_in[16];
    float* out = (float*)d_out;

    int BN = in_sizes[0] / (L * D);   // 828

    cudaFuncSetAttribute(fused_attn_kernel,
                         cudaFuncAttributeMaxDynamicSharedMemorySize, SMEM_BYTES);
    fused_attn_kernel<<<BN, NTHREADS, SMEM_BYTES>>>(
        xq, xk, xt, Wq, bq, Wk, bk, Wv, bv, Wot, bot, Wtg, btg,
        g_time, b_time, g_tgt, b_tgt, out, BN);
}

// round 3
// speedup vs baseline: 1.0024x; 1.0024x over previous
#include <cuda_runtime.h>
#include <cstdint>

#define NTHREADS 512

static constexpr int L  = 64;
static constexpr int D  = 128;
static constexpr int H  = 8;
static constexpr int DK = 16;

// Shared memory layout (floats):
//   xq   [64][128]  @ 0        (kept for residual)
//   xk   [64][128]  @ 8192     (reused as obuf in epilogue)
//   tvb  [64][128]  @ 16384
//   ctb  [64][128]  @ 24576
//   scratch         @ 32768  (14592 floats):
//     sh  [64][68], wqh/wkh/wvh [128][16], qh/kh/vh [64][16], xth [64][16]
static constexpr int SMEM_FLOATS = 32768 + 64*68 + 3*2048 + 4*1024;  // 47360
static constexpr int SMEM_BYTES  = SMEM_FLOATS * 4;                  // 189440

__global__ void __launch_bounds__(NTHREADS, 1)
fused_attn_kernel(const float* __restrict__ xq_g,
                  const float* __restrict__ xk_g,
                  const float* __restrict__ xt_g,
                  const float* __restrict__ Wq,  const float* __restrict__ bq,
                  const float* __restrict__ Wk,  const float* __restrict__ bk,
                  const float* __restrict__ Wv,  const float* __restrict__ bv,
                  const float* __restrict__ Wot, const float* __restrict__ bot,
                  const float* __restrict__ Wtg, const float* __restrict__ btg,
                  const float* __restrict__ g_time, const float* __restrict__ b_time,
                  const float* __restrict__ g_tgt,  const float* __restrict__ b_tgt,
                  float* __restrict__ out, int BN)
{
    extern __shared__ float sm[];
    float* xq  = sm;            // [64][128]
    float* xk  = sm + 8192;     // [64][128] -> obuf in epilogue
    float* tvb = sm + 16384;    // [64][128]
    float* ctb = sm + 24576;    // [64][128]
    float* scratch = sm + 32768;
    float* sh  = scratch;          // [64][68]
    float* wqh = scratch + 4352;   // [128][16]
    float* wkh = wqh + 2048;
    float* wvh = wkh + 2048;
    float* qh  = wvh + 2048;       // [64][16]
    float* kh  = qh + 1024;
    float* vh  = kh + 1024;
    float* xth = vh + 1024;        // [64][16]

    const int bn  = blockIdx.x;
    const int tid = threadIdx.x;

    const float* xq_src = xq_g + (size_t)bn * (L*D);
    const float* xk_src = xk_g + (size_t)bn * (L*D);
    const float* xt_src = xt_g + (size_t)bn * (L*D);

    const size_t attnElems = (size_t)BN * H * (L*L);
    float* tv_base = out + attnElems + (size_t)bn * (L*D);
    float* ct_base = out + attnElems + (size_t)BN * (L*D) + (size_t)bn * (L*D);

    // Load x_q, x_k tiles
    for (int i = tid; i < (L*D)/4; i += NTHREADS) {
        reinterpret_cast<float4*>(xq)[i] = reinterpret_cast<const float4*>(xq_src)[i];
        reinterpret_cast<float4*>(xk)[i] = reinterpret_cast<const float4*>(xk_src)[i];
    }
    __syncthreads();

    // ---------------- per-head stage ----------------
    for (int h = 0; h < H; ++h) {
        // stage W slices [128][16] for q,k,v and target slice [64][16]
        for (int i = tid; i < 512; i += NTHREADS) {   // 2048 floats -> 512 float4
            int d = i >> 2, c4 = i & 3;
            reinterpret_cast<float4*>(wqh)[i] =
                *(reinterpret_cast<const float4*>(Wq + d*D + h*DK) + c4);
            reinterpret_cast<float4*>(wkh)[i] =
                *(reinterpret_cast<const float4*>(Wk + d*D + h*DK) + c4);
            reinterpret_cast<float4*>(wvh)[i] =
                *(reinterpret_cast<const float4*>(Wv + d*D + h*DK) + c4);
        }
        for (int i = tid; i < 256; i += NTHREADS) {   // 1024 floats -> 256 float4
            int r = i >> 2, c4 = i & 3;
            reinterpret_cast<float4*>(xth)[i] =
                *(reinterpret_cast<const float4*>(xt_src + r*D + h*DK) + c4);
        }
        __syncthreads();

        // q_h, k_h, v_h : [64][16] = x @ Wslice + bias
        {
            const int c  = tid & 15;
            const int rb = tid >> 4;      // 0..31
            const int r0 = rb*2, r1 = r0 + 1;
            float aq0=0.f, aq1=0.f, ak0=0.f, ak1=0.f, av0=0.f, av1=0.f;
            for (int d0 = 0; d0 < D; d0 += 4) {
                float4 xa0 = *reinterpret_cast<const float4*>(xq + r0*D + d0);
                float4 xa1 = *reinterpret_cast<const float4*>(xq + r1*D + d0);
                float4 xb0 = *reinterpret_cast<const float4*>(xk + r0*D + d0);
                float4 xb1 = *reinterpret_cast<const float4*>(xk + r1*D + d0);
                float a0v[4], a1v[4], b0v[4], b1v[4];
                a0v[0]=xa0.x; a0v[1]=xa0.y; a0v[2]=xa0.z; a0v[3]=xa0.w;
                a1v[0]=xa1.x; a1v[1]=xa1.y; a1v[2]=xa1.z; a1v[3]=xa1.w;
                b0v[0]=xb0.x; b0v[1]=xb0.y; b0v[2]=xb0.z; b0v[3]=xb0.w;
                b1v[0]=xb1.x; b1v[1]=xb1.y; b1v[2]=xb1.z; b1v[3]=xb1.w;
                #pragma unroll
                for (int dd = 0; dd < 4; ++dd) {
                    float wq_ = wqh[(d0+dd)*DK + c];
                    float wk_ = wkh[(d0+dd)*DK + c];
                    float wv_ = wvh[(d0+dd)*DK + c];
                    aq0 += a0v[dd]*wq_;  aq1 += a1v[dd]*wq_;
                    ak0 += b0v[dd]*wk_;  ak1 += b1v[dd]*wk_;
                    av0 += b0v[dd]*wv_;  av1 += b1v[dd]*wv_;
                }
            }
            float bq_ = bq[h*DK + c], bk_ = bk[h*DK + c], bv_ = bv[h*DK + c];
            qh[r0*DK + c] = aq0 + bq_;  qh[r1*DK + c] = aq1 + bq_;
            kh[r0*DK + c] = ak0 + bk_;  kh[r1*DK + c] = ak1 + bk_;
            vh[r0*DK + c] = av0 + bv_;  vh[r1*DK + c] = av1 + bv_;
        }
        __syncthreads();

        // S_h [64][64] = q_h @ k_h^T * 0.25 ; write to smem + global attn output
        {
            const int kc = tid & 63;
            const int rg = tid >> 6;     // 0..7
            float kk[16];
            #pragma unroll
            for (int j = 0; j < 4; ++j) {
                float4 kv = *reinterpret_cast<const float4*>(kh + kc*DK + j*4);
                kk[4*j+0]=kv.x; kk[4*j+1]=kv.y; kk[4*j+2]=kv.z; kk[4*j+3]=kv.w;
            }
            float* attn_base = out + ((size_t)bn*H + h) * (L*L);
            #pragma unroll
            for (int i = 0; i < 8; ++i) {
                int r = rg*8 + i;
                float acc = 0.f;
                #pragma unroll
                for (int j = 0; j < 4; ++j) {
                    float4 qv = *reinterpret_cast<const float4*>(qh + r*DK + j*4);
                    acc += qv.x*kk[4*j] + qv.y*kk[4*j+1] + qv.z*kk[4*j+2] + qv.w*kk[4*j+3];
                }
                acc *= 0.25f;
                sh[r*68 + kc] = acc;
                attn_base[r*L + kc] = acc;
            }
        }
        __syncthreads();

        // tv_h = S_h @ v_h ; ct_h = S_h @ xt_h  -> accumulate head columns
        {
            const int c  = tid & 15;
            const int rb = tid >> 4;
            const int r0 = rb*2, r1 = r0 + 1;
            float atv0=0.f, atv1=0.f, act0=0.f, act1=0.f;
            for (int k0 = 0; k0 < L; k0 += 4) {
                float4 s0 = *reinterpret_cast<const float4*>(sh + r0*68 + k0);
                float4 s1 = *reinterpret_cast<const float4*>(sh + r1*68 + k0);
                float s0v[4], s1v[4];
                s0v[0]=s0.x; s0v[1]=s0.y; s0v[2]=s0.z; s0v[3]=s0.w;
                s1v[0]=s1.x; s1v[1]=s1.y; s1v[2]=s1.z; s1v[3]=s1.w;
                #pragma unroll
                for (int q = 0; q < 4; ++q) {
                    float vv = vh[(k0+q)*DK + c];
                    float tt = xth[(k0+q)*DK + c];
                    atv0 += s0v[q]*vv;  atv1 += s1v[q]*vv;
                    act0 += s0v[q]*tt;  act1 += s1v[q]*tt;
                }
            }
            tvb[r0*D + h*DK + c] = atv0;  tvb[r1*D + h*DK + c] = atv1;
            ctb[r0*D + h*DK + c] = act0;  ctb[r1*D + h*DK + c] = act1;
        }
        __syncthreads();
    }

    // ---------------- epilogue: output projections + LayerNorm ----------------
    float* obuf = xk;   // xk no longer needed
    for (int br = 0; br < 2; ++br) {
        const float* src  = br ? ctb : tvb;
        const float* W    = br ? Wtg : Wot;
        const float* bias = br ? btg : bot;

        for (int half = 0; half < 2; ++half) {
            __syncthreads();   // prior scratch/obuf consumers done
            // stage W[:, half*64 : half*64+64] -> ws [128][64]
            float* ws = scratch;
            for (int i = tid; i < (128*64)/4; i += NTHREADS) {  // 2048 float4
                int d = i >> 4, c4 = i & 15;
                reinterpret_cast<float4*>(ws)[i] =
                    *(reinterpret_cast<const float4*>(W + d*D + half*64) + c4);
            }
            __syncthreads();

            const int c0 = (tid & 15) * 4;
            const int rb = tid >> 4;
            const int r0 = rb*2, r1 = r0 + 1;
            float acc0[4], acc1[4];
            #pragma unroll
            for (int j = 0; j < 4; ++j) {
                acc0[j] = bias[half*64 + c0 + j];
                acc1[j] = acc0[j];
            }
            for (int d0 = 0; d0 < D; d0 += 4) {
                float4 a0 = *reinterpret_cast<const float4*>(src + r0*D + d0);
                float4 a1 = *reinterpret_cast<const float4*>(src + r1*D + d0);
                float a0v[4], a1v[4];
                a0v[0]=a0.x; a0v[1]=a0.y; a0v[2]=a0.z; a0v[3]=a0.w;
                a1v[0]=a1.x; a1v[1]=a1.y; a1v[2]=a1.z; a1v[3]=a1.w;
                #pragma unroll
                for (int dd = 0; dd < 4; ++dd) {
                    float4 w4 = *reinterpret_cast<const float4*>(ws + (d0+dd)*64 + c0);
                    acc0[0] += a0v[dd]*w4.x;  acc0[1] += a0v[dd]*w4.y;
                    acc0[2] += a0v[dd]*w4.z;  acc0[3] += a0v[dd]*w4.w;
                    acc1[0] += a1v[dd]*w4.x;  acc1[1] += a1v[dd]*w4.y;
                    acc1[2] += a1v[dd]*w4.z;  acc1[3] += a1v[dd]*w4.w;
                }
            }
            if (br == 0) {  // residual (time branch only)
                #pragma unroll
                for (int j = 0; j < 4; ++j) {
                    acc0[j] += xq[r0*D + half*64 + c0 + j];
                    acc1[j] += xq[r1*D + half*64 + c0 + j];
                }
            }
            *reinterpret_cast<float4*>(obuf + r0*D + half*64 + c0) =
                make_float4(acc0[0], acc0[1], acc0[2], acc0[3]);
            *reinterpret_cast<float4*>(obuf + r1*D + half*64 + c0) =
                make_float4(acc1[0], acc1[1], acc1[2], acc1[3]);
        }
        __syncthreads();

        // LayerNorm per row (population variance, eps 1e-5)
        {
            const float* g = br ? g_tgt : g_time;
            const float* b = br ? b_tgt : b_time;
            float* dst = br ? ct_base : tv_base;
            const int warp = tid >> 5, lane = tid & 31;
            #pragma unroll
            for (int i = 0; i < 4; ++i) {
                int r = warp*4 + i;
                float4 x = *reinterpret_cast<const float4*>(obuf + r*D + lane*4);
                float s1 = x.x + x.y + x.z + x.w;
                float s2 = x.x*x.x + x.y*x.y + x.z*x.z + x.w*x.w;
                #pragma unroll
                for (int o = 16; o; o >>= 1) {
                    s1 += __shfl_xor_sync(0xffffffffu, s1, o);
                    s2 += __shfl_xor_sync(0xffffffffu, s2, o);
                }
                float mean = s1 * (1.0f/128.0f);
                float var  = s2 * (1.0f/128.0f) - mean*mean;
                float rstd = rsqrtf(var + 1e-5f);
                float4 gv = *reinterpret_cast<const float4*>(g + lane*4);
                float4 bv2 = *reinterpret_cast<const float4*>(b + lane*4);
                float4 y;
                y.x = (x.x - mean)*rstd*gv.x + bv2.x;
                y.y = (x.y - mean)*rstd*gv.y + bv2.y;
                y.z = (x.z - mean)*rstd*gv.z + bv2.z;
                y.w = (x.w - mean)*rstd*gv.w + bv2.w;
                *reinterpret_cast<float4*>(dst + r*D + lane*4) = y;
            }
        }
        __syncthreads();  // obuf reused by next branch
    }
}

extern "C" void kernel_launch(void* const* d_in, const int* in_sizes, int n_in,
                              void* d_out, int out_size) {
    const float* xq   = (const float*)d_in[0];
    const float* xk   = (const float*)d_in[1];
    const float* xt   = (const float*)d_in[2];
    const float* Wq   = (const float*)d_in[3];
    const float* bq   = (const float*)d_in[4];
    const float* Wk   = (const float*)d_in[5];
    const float* bk   = (const float*)d_in[6];
    const float* Wv   = (const float*)d_in[7];
    const float* bv   = (const float*)d_in[8];
    const float* Wot  = (const float*)d_in[9];
    const float* bot  = (const float*)d_in[10];
    const float* Wtg  = (const float*)d_in[11];
    const float* btg  = (const float*)d_in[12];
    const float* g_time = (const float*)d_in[13];
    const float* b_time = (const float*)d_in[14];
    const float* g_tgt  = (const float*)d_in[15];
    const float* b_tgt  = (const float*)d_in[16];
    float* out = (float*)d_out;

    int BN = in_sizes[0] / (L * D);   // 828

    cudaFuncSetAttribute(fused_attn_kernel,
                         cudaFuncAttributeMaxDynamicSharedMemorySize, SMEM_BYTES);
    fused_attn_kernel<<<BN, NTHREADS, SMEM_BYTES>>>(
        xq, xk, xt, Wq, bq, Wk, bk, Wv, bv, Wot, bot, Wtg, btg,
        g_time, b_time, g_tgt, b_tgt, out, BN);
}